// round 14
// baseline (speedup 1.0000x reference)
#include <cuda_runtime.h>
#include <math.h>
#include <stdint.h>

#define T_STEPS 101
#define INSZ 700
#define H 512
#define OUTSZ 20
#define NBATCH 512
#define THRESH 0.5f
#define DECAY 0.5f
#define CO2 0.02f
#define NCHUNK 8

// ------------ device scratch (static: no allocs allowed) ------------
__device__ float g_X1[(size_t)T_STEPS * NBATCH * H];
__device__ float g_WrT[H * H];
__device__ float g_W2T[H * H];
__device__ float g_WoT[H * OUTSZ];
__device__ float g_ce[T_STEPS * H];
// snn chunk-carried state
__device__ float4 g_sm1[NBATCH * 128];
__device__ float4 g_sth1[NBATCH * 128];
__device__ float4 g_sm2[NBATCH * 128];
__device__ float4 g_sth2[NBATCH * 128];
__device__ unsigned g_spbG[NBATCH * 128];
__device__ float g_oaccG[NBATCH * 128];
__device__ unsigned g_sp1mG[NBATCH * 16];

// ballot-order permutation: thread t=w*32+l owns neurons 4t+s; p = s*128 + w*32 + l
__host__ __device__ __forceinline__ int p_of(int n) {
    int s = n & 3, l = (n >> 2) & 31, w = n >> 7;
    return s * 128 + w * 32 + l;
}

// ------------ transpose (validated) ------------
__global__ void k_transpose2(const float* __restrict__ wr, const float* __restrict__ w2) {
    __shared__ float tile[32][33];
    int which = blockIdx.z;
    const float* src = (which == 0) ? wr : w2;
    float* dst = (which == 0) ? g_WrT : g_W2T;
    int x  = blockIdx.x * 32 + threadIdx.x;
    int y0 = blockIdx.y * 32;
    for (int r = threadIdx.y; r < 32; r += 8)
        tile[r][threadIdx.x] = src[(size_t)(y0 + r) * H + x];
    __syncthreads();
    int xo  = blockIdx.y * 32 + threadIdx.x;
    for (int r = threadIdx.y; r < 32; r += 8) {
        int j = blockIdx.x * 32 + r;
        dst[(size_t)p_of(j) * H + xo] = tile[threadIdx.x][r];
    }
}

// ------------ merged ce + wo (validated) ------------
__global__ void k_misc(const float* __restrict__ fre, const float* __restrict__ wo) {
    if (blockIdx.x < T_STEPS) {
        int i = threadIdx.x;
        int t = blockIdx.x;
        double dt_d = 0.1 / pow(100.0, (double)i / 512.0);
        float dtf = (float)dt_d;
        float fd  = fre[i] * dtf;
        float arg = fd * (float)t;
        g_ce[t * H + i] = (float)cos((double)arg) * 0.1f;
    } else {
        int j = threadIdx.x;
        int p = p_of(j);
        for (int k = 0; k < OUTSZ; k++)
            g_WoT[p * OUTSZ + k] = wo[k * H + j];
    }
}

// ================= X1 GEMM (round-11 validated; + by_base chunk offset) =============
#define BM 128
#define BN 128
#define BK 16
#define NIT ((INSZ + BK - 1) / BK)    // 44
#define SSTR 132

__global__ __launch_bounds__(256) void k_gemm_x1(
    const float* __restrict__ A,
    const float* __restrict__ B,
    const float* __restrict__ b1,
    const float* __restrict__ br,
    int by_base)
{
    __shared__ float As[2][BK][SSTR];
    __shared__ float Bs[2][BK][SSTR];
    int tid = threadIdx.x;
    int m0 = (by_base + blockIdx.y) * BM, n0 = blockIdx.x * BN;
    int ty = tid >> 4, tx = tid & 15;

    int lrow0 = tid >> 2, lseg = (tid & 3) * 4;
    const float* Arow0 = A + (size_t)(m0 + lrow0) * INSZ;
    const float* Arow1 = A + (size_t)(m0 + lrow0 + 64) * INSZ;
    const float* Brow0 = B + (size_t)(n0 + lrow0) * INSZ;
    const float* Brow1 = B + (size_t)(n0 + lrow0 + 64) * INSZ;

    float acc[8][8];
    #pragma unroll
    for (int i = 0; i < 8; i++)
        #pragma unroll
        for (int j = 0; j < 8; j++) acc[i][j] = 0.f;

    float4 rgA0, rgA1, rgB0, rgB1;
    #define LOAD_REGS(k0)                                                          \
        do {                                                                       \
            int gk = (k0) + lseg;                                                  \
            bool ok = (gk < INSZ);                                                 \
            rgA0 = ok ? *(const float4*)(Arow0 + gk) : make_float4(0,0,0,0);       \
            rgA1 = ok ? *(const float4*)(Arow1 + gk) : make_float4(0,0,0,0);       \
            rgB0 = ok ? *(const float4*)(Brow0 + gk) : make_float4(0,0,0,0);       \
            rgB1 = ok ? *(const float4*)(Brow1 + gk) : make_float4(0,0,0,0);       \
        } while (0)

    #define STS_REGS(buf)                                                          \
        do {                                                                       \
            As[buf][lseg + 0][lrow0] = rgA0.x; As[buf][lseg + 1][lrow0] = rgA0.y;  \
            As[buf][lseg + 2][lrow0] = rgA0.z; As[buf][lseg + 3][lrow0] = rgA0.w;  \
            As[buf][lseg + 0][lrow0 + 64] = rgA1.x; As[buf][lseg + 1][lrow0 + 64] = rgA1.y; \
            As[buf][lseg + 2][lrow0 + 64] = rgA1.z; As[buf][lseg + 3][lrow0 + 64] = rgA1.w; \
            Bs[buf][lseg + 0][lrow0] = rgB0.x; Bs[buf][lseg + 1][lrow0] = rgB0.y;  \
            Bs[buf][lseg + 2][lrow0] = rgB0.z; Bs[buf][lseg + 3][lrow0] = rgB0.w;  \
            Bs[buf][lseg + 0][lrow0 + 64] = rgB1.x; Bs[buf][lseg + 1][lrow0 + 64] = rgB1.y; \
            Bs[buf][lseg + 2][lrow0 + 64] = rgB1.z; Bs[buf][lseg + 3][lrow0 + 64] = rgB1.w; \
        } while (0)

    LOAD_REGS(0);
    STS_REGS(0);
    __syncthreads();

    for (int it = 0; it < NIT; it++) {
        int buf = it & 1;
        if (it + 1 < NIT) LOAD_REGS((it + 1) * BK);
        #pragma unroll
        for (int k = 0; k < BK; k++) {
            float a8[8], b8[8];
            *(float4*)&a8[0] = *(const float4*)&As[buf][k][ty * 4];
            *(float4*)&a8[4] = *(const float4*)&As[buf][k][64 + ty * 4];
            *(float4*)&b8[0] = *(const float4*)&Bs[buf][k][tx * 4];
            *(float4*)&b8[4] = *(const float4*)&Bs[buf][k][64 + tx * 4];
            #pragma unroll
            for (int i = 0; i < 8; i++)
                #pragma unroll
                for (int j = 0; j < 8; j++)
                    acc[i][j] += a8[i] * b8[j];
        }
        if (it + 1 < NIT) STS_REGS(buf ^ 1);
        __syncthreads();
    }

    float bs[8];
    #pragma unroll
    for (int j = 0; j < 8; j++) {
        int n = n0 + ((j < 4) ? (tx * 4 + j) : (64 + tx * 4 + j - 4));
        bs[j] = b1[n] + br[n];
    }
    #pragma unroll
    for (int i = 0; i < 8; i++) {
        int m = m0 + ((i < 4) ? (ty * 4 + i) : (64 + ty * 4 + i - 4));
        float4 v0, v1;
        v0.x = acc[i][0] + bs[0]; v0.y = acc[i][1] + bs[1];
        v0.z = acc[i][2] + bs[2]; v0.w = acc[i][3] + bs[3];
        v1.x = acc[i][4] + bs[4]; v1.y = acc[i][5] + bs[5];
        v1.z = acc[i][6] + bs[6]; v1.w = acc[i][7] + bs[7];
        *(float4*)&g_X1[(size_t)m * H + n0 + tx * 4] = v0;
        *(float4*)&g_X1[(size_t)m * H + n0 + 64 + tx * 4] = v1;
    }
}

// ------------ single-mask list compaction (validated) ------------
__device__ __forceinline__ void build_list1(const unsigned* msk, unsigned* lst, int* cnt, int tid) {
    if (tid < 32) {
        unsigned u = (tid < 16) ? msk[tid] : 0u;
        int c = __popc(u);
        int off = c;
        #pragma unroll
        for (int d = 1; d < 32; d <<= 1) {
            int v = __shfl_up_sync(0xffffffffu, off, d);
            if (tid >= d) off += v;
        }
        off -= c;
        if (tid == 31) *cnt = off;
        while (u) {
            int b = __ffs(u) - 1;
            u &= u - 1;
            lst[off++] = (unsigned)(tid * 32 + b);
        }
    }
}

#define GATHER4(W4, lst, cnt, acc)                                         \
    {                                                                      \
        int a = 0;                                                         \
        for (; a + 8 <= (cnt); a += 8) {                                   \
            uint4 eA = *(const uint4*)&(lst)[a];                           \
            uint4 eB = *(const uint4*)&(lst)[a + 4];                       \
            float4 v0 = W4[(eA.x << 7) + tid];                             \
            float4 v1 = W4[(eA.y << 7) + tid];                             \
            float4 v2 = W4[(eA.z << 7) + tid];                             \
            float4 v3 = W4[(eA.w << 7) + tid];                             \
            float4 v4 = W4[(eB.x << 7) + tid];                             \
            float4 v5 = W4[(eB.y << 7) + tid];                             \
            float4 v6 = W4[(eB.z << 7) + tid];                             \
            float4 v7 = W4[(eB.w << 7) + tid];                             \
            acc.x += v0.x; acc.y += v0.y; acc.z += v0.z; acc.w += v0.w;    \
            acc.x += v1.x; acc.y += v1.y; acc.z += v1.z; acc.w += v1.w;    \
            acc.x += v2.x; acc.y += v2.y; acc.z += v2.z; acc.w += v2.w;    \
            acc.x += v3.x; acc.y += v3.y; acc.z += v3.z; acc.w += v3.w;    \
            acc.x += v4.x; acc.y += v4.y; acc.z += v4.z; acc.w += v4.w;    \
            acc.x += v5.x; acc.y += v5.y; acc.z += v5.z; acc.w += v5.w;    \
            acc.x += v6.x; acc.y += v6.y; acc.z += v6.z; acc.w += v6.w;    \
            acc.x += v7.x; acc.y += v7.y; acc.z += v7.z; acc.w += v7.w;    \
        }                                                                  \
        for (; a < (cnt); a++) {                                           \
            float4 v = W4[((lst)[a] << 7) + tid];                          \
            acc.x += v.x; acc.y += v.y; acc.z += v.z; acc.w += v.w;        \
        }                                                                  \
    }

// ================= SNN chunk: 1 sample/CTA, state carried between chunks ============
__global__ __launch_bounds__(128, 4) void k_snn(
    const float* __restrict__ b2,
    const float* __restrict__ bo,
    float* __restrict__ out,
    int t0, int tcnt, int first, int last)
{
    int tid = threadIdx.x;
    int wi = tid >> 5, lane = tid & 31;
    int samp = blockIdx.x;
    size_t sbase = (size_t)samp * 128 + tid;

    __shared__ unsigned sp1m[16];
    __shared__ unsigned sp2m[16];
    __shared__ __align__(16) unsigned lstA[512];
    __shared__ __align__(16) unsigned lstB[512];
    __shared__ int s_cntA, s_cntB;
    __shared__ float s_red[100];

    float mem1[4], th1[4], mem2[4], th2[4];
    unsigned sp1bits, sp2bits;
    float oacc;
    int rq = tid / OUTSZ, ok = tid % OUTSZ;
    bool odo = (tid < 120);

    if (first) {
        #pragma unroll
        for (int s = 0; s < 4; s++) {
            mem1[s] = 0.f; mem2[s] = 0.f;
            th1[s] = THRESH; th2[s] = THRESH;
        }
        sp1bits = 0; sp2bits = 0; oacc = 0.f;
        if (tid < 16) sp1m[tid] = 0u;
        if (tid == 0) { s_cntA = 0; s_cntB = 0; }
        __syncthreads();
    } else {
        float4 v;
        v = g_sm1[sbase];  mem1[0] = v.x; mem1[1] = v.y; mem1[2] = v.z; mem1[3] = v.w;
        v = g_sth1[sbase]; th1[0] = v.x;  th1[1] = v.y;  th1[2] = v.z;  th1[3] = v.w;
        v = g_sm2[sbase];  mem2[0] = v.x; mem2[1] = v.y; mem2[2] = v.z; mem2[3] = v.w;
        v = g_sth2[sbase]; th2[0] = v.x;  th2[1] = v.y;  th2[2] = v.z;  th2[3] = v.w;
        unsigned sb = g_spbG[sbase];
        sp1bits = sb & 0xFu; sp2bits = sb >> 4;
        oacc = g_oaccG[sbase];
        if (tid < 16) sp1m[tid] = g_sp1mG[samp * 16 + tid];
        if (tid == 0) s_cntB = 0;
        __syncthreads();
        build_list1(sp1m, lstA, &s_cntA, tid);
        __syncthreads();
    }

    float4 b2v = *(const float4*)&b2[4 * tid];
    const float4* Wr4 = (const float4*)g_WrT;
    const float4* W24 = (const float4*)g_W2T;

    for (int tt = 0; tt < tcnt; tt++) {
        int t = t0 + tt;
        float4 c4 = *(const float4*)&g_ce[t * H + 4 * tid];
        float4 x4 = *(const float4*)&g_X1[((size_t)t * NBATCH + samp) * H + 4 * tid];

        // ===== layer 1 =====
        int cnt = s_cntA;
        float4 acc = make_float4(0.f, 0.f, 0.f, 0.f);
        GATHER4(Wr4, lstA, cnt, acc);

        unsigned ns1 = 0;
        {
            float hh[4] = {x4.x + acc.x, x4.y + acc.y, x4.z + acc.z, x4.w + acc.w};
            float cc[4] = {c4.x, c4.y, c4.z, c4.w};
            #pragma unroll
            for (int s = 0; s < 4; s++) {
                th1[s] = (th1[s] + mem1[s] * cc[s]) - (th1[s] - THRESH) * CO2;
                float dk = ((sp1bits >> s) & 1u) ? 0.f : DECAY;
                mem1[s] = mem1[s] * dk + hh[s];
                if (mem1[s] > th1[s]) ns1 |= 1u << s;
            }
        }
        #pragma unroll
        for (int s = 0; s < 4; s++) {
            unsigned bl = __ballot_sync(0xffffffffu, (ns1 >> s) & 1u);
            if (lane == 0) sp1m[s * 4 + wi] = bl;
        }
        sp1bits = ns1;
        __syncthreads();
        build_list1(sp1m, lstA, &s_cntA, tid);
        __syncthreads();

        // ===== layer 2 =====
        cnt = s_cntA;
        acc = make_float4(0.f, 0.f, 0.f, 0.f);
        GATHER4(W24, lstA, cnt, acc);

        unsigned ns2 = 0;
        {
            float hh[4] = {acc.x + b2v.x, acc.y + b2v.y, acc.z + b2v.z, acc.w + b2v.w};
            float cc[4] = {c4.x, c4.y, c4.z, c4.w};
            #pragma unroll
            for (int s = 0; s < 4; s++) {
                th2[s] = (th2[s] + mem2[s] * cc[s]) - (th2[s] - THRESH) * CO2;
                float dk = ((sp2bits >> s) & 1u) ? 0.f : DECAY;
                mem2[s] = mem2[s] * dk + hh[s];
                if (mem2[s] > th2[s]) ns2 |= 1u << s;
            }
        }
        #pragma unroll
        for (int s = 0; s < 4; s++) {
            unsigned bl = __ballot_sync(0xffffffffu, (ns2 >> s) & 1u);
            if (lane == 0) sp2m[s * 4 + wi] = bl;
        }
        sp2bits = ns2;
        __syncthreads();
        build_list1(sp2m, lstB, &s_cntB, tid);
        __syncthreads();

        // ===== readout =====
        if (odo) {
            int cb = s_cntB;
            int a = rq;
            for (; a + 18 < cb; a += 24) {
                unsigned e0 = lstB[a], e1 = lstB[a + 6], e2 = lstB[a + 12], e3 = lstB[a + 18];
                float w0 = g_WoT[e0 * OUTSZ + ok];
                float w1 = g_WoT[e1 * OUTSZ + ok];
                float w2 = g_WoT[e2 * OUTSZ + ok];
                float w3 = g_WoT[e3 * OUTSZ + ok];
                oacc += w0; oacc += w1; oacc += w2; oacc += w3;
            }
            for (; a < cb; a += 6)
                oacc += g_WoT[lstB[a] * OUTSZ + ok];
        }
    }

    if (!last) {
        g_sm1[sbase]  = make_float4(mem1[0], mem1[1], mem1[2], mem1[3]);
        g_sth1[sbase] = make_float4(th1[0], th1[1], th1[2], th1[3]);
        g_sm2[sbase]  = make_float4(mem2[0], mem2[1], mem2[2], mem2[3]);
        g_sth2[sbase] = make_float4(th2[0], th2[1], th2[2], th2[3]);
        g_spbG[sbase] = sp1bits | (sp2bits << 4);
        g_oaccG[sbase] = oacc;
        if (tid < 16) g_sp1mG[samp * 16 + tid] = sp1m[tid];
    } else {
        __syncthreads();
        if (odo && rq > 0) s_red[(rq - 1) * OUTSZ + ok] = oacc;
        __syncthreads();
        if (tid < OUTSZ) {
            float tot = oacc;
            #pragma unroll
            for (int i = 0; i < 5; i++) tot += s_red[i * OUTSZ + tid];
            out[(size_t)samp * OUTSZ + tid] = tot / (float)T_STEPS + bo[tid];
        }
    }
}

// ================= launch: chunked two-stream pipeline (fork/join via events) =======
extern "C" void kernel_launch(void* const* d_in, const int* in_sizes, int n_in,
                              void* d_out, int out_size) {
    const float* input = (const float*)d_in[0];
    const float* w1    = (const float*)d_in[1];
    const float* b1    = (const float*)d_in[2];
    const float* wr    = (const float*)d_in[3];
    const float* br    = (const float*)d_in[4];
    const float* w2    = (const float*)d_in[5];
    const float* b2    = (const float*)d_in[6];
    const float* wo    = (const float*)d_in[7];
    const float* bo    = (const float*)d_in[8];
    const float* fre   = (const float*)d_in[9];
    float* out = (float*)d_out;

    // fresh per call (kernel_launch runs only for correctness + capture; no device mem)
    cudaStream_t s2;
    cudaStreamCreateWithFlags(&s2, cudaStreamNonBlocking);
    cudaEvent_t evg[NCHUNK], evj;
    for (int c = 0; c < NCHUNK; c++)
        cudaEventCreateWithFlags(&evg[c], cudaEventDisableTiming);
    cudaEventCreateWithFlags(&evj, cudaEventDisableTiming);

    k_transpose2<<<dim3(16, 16, 2), dim3(32, 8)>>>(wr, w2);
    k_misc<<<T_STEPS + 1, H>>>(fre, wo);

    int t0 = 0;
    for (int c = 0; c < NCHUNK; c++) {
        int tc = (c < NCHUNK - 1) ? 13 : (T_STEPS - 13 * (NCHUNK - 1));  // 13..13,10
        k_gemm_x1<<<dim3(H / BN, tc * 4), 256>>>(input, w1, b1, br, t0 * 4);
        cudaEventRecord(evg[c], 0);
        t0 += tc;
    }
    t0 = 0;
    for (int c = 0; c < NCHUNK; c++) {
        int tc = (c < NCHUNK - 1) ? 13 : (T_STEPS - 13 * (NCHUNK - 1));
        cudaStreamWaitEvent(s2, evg[c], 0);
        k_snn<<<NBATCH, 128, 0, s2>>>(b2, bo, out, t0, tc,
                                      c == 0 ? 1 : 0, c == NCHUNK - 1 ? 1 : 0);
        t0 += tc;
    }
    cudaEventRecord(evj, s2);
    cudaStreamWaitEvent(0, evj, 0);   // join fork back to capture stream
}

// round 15
// speedup vs baseline: 1.1080x; 1.1080x over previous
#include <cuda_runtime.h>
#include <math.h>
#include <stdint.h>

#define T_STEPS 101
#define INSZ 700
#define H 512
#define OUTSZ 20
#define NBATCH 512
#define THRESH 0.5f
#define DECAY 0.5f
#define CO2 0.02f

// ------------ device scratch (static: no allocs allowed) ------------
__device__ float g_X1[(size_t)T_STEPS * NBATCH * H];
__device__ float g_WrT[H * H];
__device__ float g_W2T[H * H];
__device__ float g_WoT[H * OUTSZ];
__device__ float g_ce[T_STEPS * H];

// ballot-order permutation: thread t=w*32+l owns neurons 4t+s; p = s*128 + w*32 + l
__host__ __device__ __forceinline__ int p_of(int n) {
    int s = n & 3, l = (n >> 2) & 31, w = n >> 7;
    return s * 128 + w * 32 + l;
}

// ------------ transpose (validated) ------------
__global__ void k_transpose2(const float* __restrict__ wr, const float* __restrict__ w2) {
    __shared__ float tile[32][33];
    int which = blockIdx.z;
    const float* src = (which == 0) ? wr : w2;
    float* dst = (which == 0) ? g_WrT : g_W2T;
    int x  = blockIdx.x * 32 + threadIdx.x;
    int y0 = blockIdx.y * 32;
    for (int r = threadIdx.y; r < 32; r += 8)
        tile[r][threadIdx.x] = src[(size_t)(y0 + r) * H + x];
    __syncthreads();
    int xo  = blockIdx.y * 32 + threadIdx.x;
    for (int r = threadIdx.y; r < 32; r += 8) {
        int j = blockIdx.x * 32 + r;
        dst[(size_t)p_of(j) * H + xo] = tile[threadIdx.x][r];
    }
}

// ------------ merged ce + wo (validated) ------------
__global__ void k_misc(const float* __restrict__ fre, const float* __restrict__ wo) {
    if (blockIdx.x < T_STEPS) {
        int i = threadIdx.x;
        int t = blockIdx.x;
        double dt_d = 0.1 / pow(100.0, (double)i / 512.0);
        float dtf = (float)dt_d;
        float fd  = fre[i] * dtf;
        float arg = fd * (float)t;
        g_ce[t * H + i] = (float)cos((double)arg) * 0.1f;
    } else {
        int j = threadIdx.x;
        int p = p_of(j);
        for (int k = 0; k < OUTSZ; k++)
            g_WoT[p * OUTSZ + k] = wo[k * H + j];
    }
}

// ================= X1 GEMM (round-11 validated verbatim, 782us, X1 bit-exact) ======
#define BM 128
#define BN 128
#define BK 16
#define NIT ((INSZ + BK - 1) / BK)    // 44
#define SSTR 132

__global__ __launch_bounds__(256) void k_gemm_x1(
    const float* __restrict__ A,
    const float* __restrict__ B,
    const float* __restrict__ b1,
    const float* __restrict__ br)
{
    __shared__ float As[2][BK][SSTR];
    __shared__ float Bs[2][BK][SSTR];
    int tid = threadIdx.x;
    int m0 = blockIdx.y * BM, n0 = blockIdx.x * BN;
    int ty = tid >> 4, tx = tid & 15;

    int lrow0 = tid >> 2, lseg = (tid & 3) * 4;
    const float* Arow0 = A + (size_t)(m0 + lrow0) * INSZ;
    const float* Arow1 = A + (size_t)(m0 + lrow0 + 64) * INSZ;
    const float* Brow0 = B + (size_t)(n0 + lrow0) * INSZ;
    const float* Brow1 = B + (size_t)(n0 + lrow0 + 64) * INSZ;

    float acc[8][8];
    #pragma unroll
    for (int i = 0; i < 8; i++)
        #pragma unroll
        for (int j = 0; j < 8; j++) acc[i][j] = 0.f;

    float4 rgA0, rgA1, rgB0, rgB1;
    #define LOAD_REGS(k0)                                                          \
        do {                                                                       \
            int gk = (k0) + lseg;                                                  \
            bool ok = (gk < INSZ);                                                 \
            rgA0 = ok ? *(const float4*)(Arow0 + gk) : make_float4(0,0,0,0);       \
            rgA1 = ok ? *(const float4*)(Arow1 + gk) : make_float4(0,0,0,0);       \
            rgB0 = ok ? *(const float4*)(Brow0 + gk) : make_float4(0,0,0,0);       \
            rgB1 = ok ? *(const float4*)(Brow1 + gk) : make_float4(0,0,0,0);       \
        } while (0)

    #define STS_REGS(buf)                                                          \
        do {                                                                       \
            As[buf][lseg + 0][lrow0] = rgA0.x; As[buf][lseg + 1][lrow0] = rgA0.y;  \
            As[buf][lseg + 2][lrow0] = rgA0.z; As[buf][lseg + 3][lrow0] = rgA0.w;  \
            As[buf][lseg + 0][lrow0 + 64] = rgA1.x; As[buf][lseg + 1][lrow0 + 64] = rgA1.y; \
            As[buf][lseg + 2][lrow0 + 64] = rgA1.z; As[buf][lseg + 3][lrow0 + 64] = rgA1.w; \
            Bs[buf][lseg + 0][lrow0] = rgB0.x; Bs[buf][lseg + 1][lrow0] = rgB0.y;  \
            Bs[buf][lseg + 2][lrow0] = rgB0.z; Bs[buf][lseg + 3][lrow0] = rgB0.w;  \
            Bs[buf][lseg + 0][lrow0 + 64] = rgB1.x; Bs[buf][lseg + 1][lrow0 + 64] = rgB1.y; \
            Bs[buf][lseg + 2][lrow0 + 64] = rgB1.z; Bs[buf][lseg + 3][lrow0 + 64] = rgB1.w; \
        } while (0)

    LOAD_REGS(0);
    STS_REGS(0);
    __syncthreads();

    for (int it = 0; it < NIT; it++) {
        int buf = it & 1;
        if (it + 1 < NIT) LOAD_REGS((it + 1) * BK);
        #pragma unroll
        for (int k = 0; k < BK; k++) {
            float a8[8], b8[8];
            *(float4*)&a8[0] = *(const float4*)&As[buf][k][ty * 4];
            *(float4*)&a8[4] = *(const float4*)&As[buf][k][64 + ty * 4];
            *(float4*)&b8[0] = *(const float4*)&Bs[buf][k][tx * 4];
            *(float4*)&b8[4] = *(const float4*)&Bs[buf][k][64 + tx * 4];
            #pragma unroll
            for (int i = 0; i < 8; i++)
                #pragma unroll
                for (int j = 0; j < 8; j++)
                    acc[i][j] += a8[i] * b8[j];
        }
        if (it + 1 < NIT) STS_REGS(buf ^ 1);
        __syncthreads();
    }

    float bs[8];
    #pragma unroll
    for (int j = 0; j < 8; j++) {
        int n = n0 + ((j < 4) ? (tx * 4 + j) : (64 + tx * 4 + j - 4));
        bs[j] = b1[n] + br[n];
    }
    #pragma unroll
    for (int i = 0; i < 8; i++) {
        int m = m0 + ((i < 4) ? (ty * 4 + i) : (64 + ty * 4 + i - 4));
        float4 v0, v1;
        v0.x = acc[i][0] + bs[0]; v0.y = acc[i][1] + bs[1];
        v0.z = acc[i][2] + bs[2]; v0.w = acc[i][3] + bs[3];
        v1.x = acc[i][4] + bs[4]; v1.y = acc[i][5] + bs[5];
        v1.z = acc[i][6] + bs[6]; v1.w = acc[i][7] + bs[7];
        *(float4*)&g_X1[(size_t)m * H + n0 + tx * 4] = v0;
        *(float4*)&g_X1[(size_t)m * H + n0 + 64 + tx * 4] = v1;
    }
}

// ------------ single-mask list compaction (validated) ------------
__device__ __forceinline__ void build_list1(const unsigned* msk, unsigned* lst, int* cnt, int tid) {
    if (tid < 32) {
        unsigned u = (tid < 16) ? msk[tid] : 0u;
        int c = __popc(u);
        int off = c;
        #pragma unroll
        for (int d = 1; d < 32; d <<= 1) {
            int v = __shfl_up_sync(0xffffffffu, off, d);
            if (tid >= d) off += v;
        }
        off -= c;
        if (tid == 31) *cnt = off;
        while (u) {
            int b = __ffs(u) - 1;
            u &= u - 1;
            lst[off++] = (unsigned)(tid * 32 + b);
        }
    }
}

#define F4ADD(acc, v) do { acc.x += (v).x; acc.y += (v).y; acc.z += (v).z; acc.w += (v).w; } while (0)

// dual gather: per list entry, read W2 row (-> accA, used this step) and
// Wr row (-> accB, carried to next step's layer-1). 16 float4 loads in flight.
// Accumulation stays ascending-list into fresh accumulators -> bit-exact.
#define DGATHER8(lst, cnt, accA, accB)                                     \
    {                                                                      \
        int a = 0;                                                         \
        for (; a + 8 <= (cnt); a += 8) {                                   \
            uint4 eA = *(const uint4*)&(lst)[a];                           \
            uint4 eB = *(const uint4*)&(lst)[a + 4];                       \
            float4 p0 = W24[(eA.x << 7) + tid];                            \
            float4 q0 = Wr4[(eA.x << 7) + tid];                            \
            float4 p1 = W24[(eA.y << 7) + tid];                            \
            float4 q1 = Wr4[(eA.y << 7) + tid];                            \
            float4 p2 = W24[(eA.z << 7) + tid];                            \
            float4 q2 = Wr4[(eA.z << 7) + tid];                            \
            float4 p3 = W24[(eA.w << 7) + tid];                            \
            float4 q3 = Wr4[(eA.w << 7) + tid];                            \
            float4 p4 = W24[(eB.x << 7) + tid];                            \
            float4 q4 = Wr4[(eB.x << 7) + tid];                            \
            float4 p5 = W24[(eB.y << 7) + tid];                            \
            float4 q5 = Wr4[(eB.y << 7) + tid];                            \
            float4 p6 = W24[(eB.z << 7) + tid];                            \
            float4 q6 = Wr4[(eB.z << 7) + tid];                            \
            float4 p7 = W24[(eB.w << 7) + tid];                            \
            float4 q7 = Wr4[(eB.w << 7) + tid];                            \
            F4ADD(accA, p0); F4ADD(accB, q0);                              \
            F4ADD(accA, p1); F4ADD(accB, q1);                              \
            F4ADD(accA, p2); F4ADD(accB, q2);                              \
            F4ADD(accA, p3); F4ADD(accB, q3);                              \
            F4ADD(accA, p4); F4ADD(accB, q4);                              \
            F4ADD(accA, p5); F4ADD(accB, q5);                              \
            F4ADD(accA, p6); F4ADD(accB, q6);                              \
            F4ADD(accA, p7); F4ADD(accB, q7);                              \
        }                                                                  \
        for (; a < (cnt); a++) {                                           \
            unsigned e = (lst)[a];                                         \
            float4 p = W24[(e << 7) + tid];                                \
            float4 q = Wr4[(e << 7) + tid];                                \
            F4ADD(accA, p); F4ADD(accB, q);                                \
        }                                                                  \
    }

// ================= SNN: 1 sample/CTA, cross-step pipelined dual gather ==============
__global__ __launch_bounds__(128, 4) void k_snn(
    const float* __restrict__ b2,
    const float* __restrict__ bo,
    float* __restrict__ out)
{
    int tid = threadIdx.x;
    int wi = tid >> 5, lane = tid & 31;
    int samp = blockIdx.x;

    __shared__ unsigned sp1m[16];
    __shared__ unsigned sp2m[16];
    __shared__ __align__(16) unsigned lstA[512];
    __shared__ __align__(16) unsigned lstB[512];
    __shared__ int s_cntA, s_cntB;
    __shared__ float s_red[100];

    float mem1[4], th1[4], mem2[4], th2[4];
    #pragma unroll
    for (int s = 0; s < 4; s++) {
        mem1[s] = 0.f; mem2[s] = 0.f;
        th1[s] = THRESH; th2[s] = THRESH;
    }
    unsigned sp1bits = 0, sp2bits = 0;

    float oacc = 0.f;
    int rq = tid / OUTSZ, ok = tid % OUTSZ;
    bool odo = (tid < 120);

    if (tid < 16) { sp1m[tid] = 0u; sp2m[tid] = 0u; }
    if (tid == 0) { s_cntA = 0; s_cntB = 0; }
    __syncthreads();

    float4 b2v = *(const float4*)&b2[4 * tid];
    const float4* Wr4 = (const float4*)g_WrT;
    const float4* W24 = (const float4*)g_W2T;

    // carried recurrent input: accWr = Wr @ sp1(t-1); zero for t=0
    float4 accWr = make_float4(0.f, 0.f, 0.f, 0.f);

    for (int t = 0; t < T_STEPS; t++) {
        float4 c4 = *(const float4*)&g_ce[t * H + 4 * tid];
        float4 x4 = *(const float4*)&g_X1[((size_t)t * NBATCH + samp) * H + 4 * tid];

        // ===== layer 1 update (uses carried accWr) =====
        unsigned ns1 = 0;
        {
            float hh[4] = {x4.x + accWr.x, x4.y + accWr.y, x4.z + accWr.z, x4.w + accWr.w};
            float cc[4] = {c4.x, c4.y, c4.z, c4.w};
            #pragma unroll
            for (int s = 0; s < 4; s++) {
                th1[s] = (th1[s] + mem1[s] * cc[s]) - (th1[s] - THRESH) * CO2;
                float dk = ((sp1bits >> s) & 1u) ? 0.f : DECAY;
                mem1[s] = mem1[s] * dk + hh[s];
                if (mem1[s] > th1[s]) ns1 |= 1u << s;
            }
        }
        #pragma unroll
        for (int s = 0; s < 4; s++) {
            unsigned bl = __ballot_sync(0xffffffffu, (ns1 >> s) & 1u);
            if (lane == 0) sp1m[s * 4 + wi] = bl;
        }
        sp1bits = ns1;
        __syncthreads();                        // (1) prev dual-gather reads done + masks
        build_list1(sp1m, lstA, &s_cntA, tid);  // lstA = sp1(t)
        __syncthreads();                        // (2)

        // ===== dual gather over sp1(t): W2 (now) + Wr (next step) =====
        int cnt = s_cntA;
        float4 accW2 = make_float4(0.f, 0.f, 0.f, 0.f);
        float4 accWrN = make_float4(0.f, 0.f, 0.f, 0.f);
        DGATHER8(lstA, cnt, accW2, accWrN);

        // ===== layer 2 update =====
        unsigned ns2 = 0;
        {
            float hh[4] = {accW2.x + b2v.x, accW2.y + b2v.y, accW2.z + b2v.z, accW2.w + b2v.w};
            float cc[4] = {c4.x, c4.y, c4.z, c4.w};
            #pragma unroll
            for (int s = 0; s < 4; s++) {
                th2[s] = (th2[s] + mem2[s] * cc[s]) - (th2[s] - THRESH) * CO2;
                float dk = ((sp2bits >> s) & 1u) ? 0.f : DECAY;
                mem2[s] = mem2[s] * dk + hh[s];
                if (mem2[s] > th2[s]) ns2 |= 1u << s;
            }
        }
        #pragma unroll
        for (int s = 0; s < 4; s++) {
            unsigned bl = __ballot_sync(0xffffffffu, (ns2 >> s) & 1u);
            if (lane == 0) sp2m[s * 4 + wi] = bl;
        }
        sp2bits = ns2;
        __syncthreads();                        // (3)
        build_list1(sp2m, lstB, &s_cntB, tid);
        __syncthreads();                        // (4)

        // ===== readout over lstB: 6 strided groups =====
        if (odo) {
            int cb = s_cntB;
            int a = rq;
            for (; a + 18 < cb; a += 24) {
                unsigned e0 = lstB[a], e1 = lstB[a + 6], e2 = lstB[a + 12], e3 = lstB[a + 18];
                float w0 = g_WoT[e0 * OUTSZ + ok];
                float w1 = g_WoT[e1 * OUTSZ + ok];
                float w2 = g_WoT[e2 * OUTSZ + ok];
                float w3 = g_WoT[e3 * OUTSZ + ok];
                oacc += w0; oacc += w1; oacc += w2; oacc += w3;
            }
            for (; a < cb; a += 6)
                oacc += g_WoT[lstB[a] * OUTSZ + ok];
        }

        accWr = accWrN;   // carry Wr @ sp1(t) into step t+1
    }

    // readout reduction across the 6 groups
    __syncthreads();
    if (odo && rq > 0) s_red[(rq - 1) * OUTSZ + ok] = oacc;
    __syncthreads();
    if (tid < OUTSZ) {
        float tot = oacc;
        #pragma unroll
        for (int i = 0; i < 5; i++) tot += s_red[i * OUTSZ + tid];
        out[(size_t)samp * OUTSZ + tid] = tot / (float)T_STEPS + bo[tid];
    }
}

// ================= launch: serial, 4 launches, k_snn at profiled slot (idx 3) =======
extern "C" void kernel_launch(void* const* d_in, const int* in_sizes, int n_in,
                              void* d_out, int out_size) {
    const float* input = (const float*)d_in[0];
    const float* w1    = (const float*)d_in[1];
    const float* b1    = (const float*)d_in[2];
    const float* wr    = (const float*)d_in[3];
    const float* br    = (const float*)d_in[4];
    const float* w2    = (const float*)d_in[5];
    const float* b2    = (const float*)d_in[6];
    const float* wo    = (const float*)d_in[7];
    const float* bo    = (const float*)d_in[8];
    const float* fre   = (const float*)d_in[9];
    float* out = (float*)d_out;

    k_transpose2<<<dim3(16, 16, 2), dim3(32, 8)>>>(wr, w2);        // idx 0
    k_misc<<<T_STEPS + 1, H>>>(fre, wo);                           // idx 1
    k_gemm_x1<<<dim3(H / BN, (T_STEPS * NBATCH) / BM), 256>>>(     // idx 2
        input, w1, b1, br);
    k_snn<<<NBATCH, 128>>>(b2, bo, out);                           // idx 3 (profiled)
}